// round 1
// baseline (speedup 1.0000x reference)
#include <cuda_runtime.h>
#include <math.h>

// Fixed problem sizes (with headroom). Scratch lives in __device__ globals
// (no dynamic allocation allowed).
#define MAXN 524288
#define MAXS 24576

__device__ int   d_segstart[MAXS + 1];
__device__ float d_logit[MAXN];       // spill path for segments > 256 nodes
__device__ float d_e[MAXN];           // spill path
__device__ float d_gsum[MAXS];        // sum of gates per segment (= denom/(denom+eps))
__device__ float d_pooled[(size_t)MAXS * 256];  // sum_n gate_n * x_n

// ---------------------------------------------------------------------------
// Kernel 1: segment start offsets via binary search (index is sorted).
// seg_start[s] = first n with index[n] >= s ; seg_start[S] = N.
// ---------------------------------------------------------------------------
__global__ void seg_start_kernel(const int* __restrict__ index, int N, int S) {
    int s = blockIdx.x * blockDim.x + threadIdx.x;
    if (s > S) return;
    int lo = 0, hi = N;
    while (lo < hi) {
        int mid = (lo + hi) >> 1;
        if (index[mid] < s) lo = mid + 1; else hi = mid;
    }
    d_segstart[s] = lo;
}

// ---------------------------------------------------------------------------
// Kernel 2: one block per segment. Computes attention logits, segment max,
// weighted-exp gates, denominator, and the gate-weighted pooled x row.
// No atomics: segments are contiguous (index sorted).
// ---------------------------------------------------------------------------
__global__ __launch_bounds__(256) void pool_kernel(
    const float* __restrict__ x,     // [N,256]
    const float* __restrict__ wts,   // [N] (strictly positive)
    const float* __restrict__ Wg,    // [256]
    const float* __restrict__ bg,    // [1]
    const float* __restrict__ p)     // [1]
{
    __shared__ float4 sWg4[64];
    __shared__ float  sVal[256];   // logits -> e -> gates (small-segment path)
    __shared__ float  sRed[8];
    __shared__ float  sBC[2];      // [0]=inv, [1]=gsum
    __shared__ float4 sPool[256];  // cross-node-slot reduction buffer

    const int s   = blockIdx.x;
    const int tid = threadIdx.x;
    const int beg = d_segstart[s];
    const int end = d_segstart[s + 1];
    const int cnt = end - beg;
    const bool small = (cnt <= 256);

    if (tid < 64) sWg4[tid] = ((const float4*)Wg)[tid];
    const float bg0 = bg[0];
    const float p0  = p[0];
    __syncthreads();

    const int warp = tid >> 5, lane = tid & 31;
    const float4* __restrict__ x4 = (const float4*)x;

    // -------- Phase A: logits + per-warp running max --------
    float wmax = -INFINITY;
    for (int i = warp; i < cnt; i += 8) {
        const float4* row = x4 + (size_t)(beg + i) * 64;
        float4 a = row[lane];
        float4 b = row[lane + 32];
        float4 ga = sWg4[lane];
        float4 gb = sWg4[lane + 32];
        float sum = a.x * ga.x + a.y * ga.y + a.z * ga.z + a.w * ga.w
                  + b.x * gb.x + b.y * gb.y + b.z * gb.z + b.w * gb.w;
        #pragma unroll
        for (int off = 16; off; off >>= 1)
            sum += __shfl_xor_sync(0xffffffffu, sum, off);
        if (lane == 0) {
            float lg = sum + bg0;
            if (small) sVal[i] = lg; else d_logit[beg + i] = lg;
            wmax = fmaxf(wmax, lg);
        }
    }
    if (lane == 0) sRed[warp] = wmax;
    __syncthreads();
    if (tid == 0) {
        float m = sRed[0];
        #pragma unroll
        for (int i = 1; i < 8; i++) m = fmaxf(m, sRed[i]);
        sRed[0] = m;
    }
    __syncthreads();
    const float mx = sRed[0];
    __syncthreads();  // sRed reused below

    // -------- Phase B: e = w^p * exp(logit - mx), denominator --------
    float psum = 0.0f;
    if (small) {
        if (tid < cnt) {
            float e = powf(wts[beg + tid], p0) * expf(sVal[tid] - mx);
            sVal[tid] = e;
            psum = e;
        }
    } else {
        for (int i = tid; i < cnt; i += 256) {
            float e = powf(wts[beg + i], p0) * expf(d_logit[beg + i] - mx);
            d_e[beg + i] = e;
            psum += e;
        }
    }
    #pragma unroll
    for (int off = 16; off; off >>= 1)
        psum += __shfl_xor_sync(0xffffffffu, psum, off);
    if (lane == 0) sRed[warp] = psum;
    __syncthreads();
    if (tid == 0) {
        float d = 0.0f;
        #pragma unroll
        for (int i = 0; i < 8; i++) d += sRed[i];
        float inv = 1.0f / (d + 1e-10f);
        sBC[0] = inv;
        sBC[1] = d * inv;   // sum of gates (for bm term)
    }
    __syncthreads();
    const float inv = sBC[0];

    // -------- Phase C: pooled[s,:] = sum_i gate_i * x[i,:] --------
    // Thread layout: ns = node-slot (0..3), f = feature group of 4 floats.
    const int f  = tid & 63;
    const int ns = tid >> 6;
    float4 acc = make_float4(0.f, 0.f, 0.f, 0.f);

    if (small) {
        if (tid < cnt) sVal[tid] *= inv;   // e -> gate
        __syncthreads();
        for (int i = ns; i < cnt; i += 4) {
            float g = sVal[i];
            float4 v = x4[(size_t)(beg + i) * 64 + f];
            acc.x += g * v.x; acc.y += g * v.y;
            acc.z += g * v.z; acc.w += g * v.w;
        }
    } else {
        for (int base = 0; base < cnt; base += 256) {
            int m = min(256, cnt - base);
            __syncthreads();
            if (tid < m) sVal[tid] = d_e[beg + base + tid] * inv;
            __syncthreads();
            for (int i = ns; i < m; i += 4) {
                float g = sVal[i];
                float4 v = x4[(size_t)(beg + base + i) * 64 + f];
                acc.x += g * v.x; acc.y += g * v.y;
                acc.z += g * v.z; acc.w += g * v.w;
            }
        }
    }

    sPool[tid] = acc;
    __syncthreads();
    if (tid < 64) {
        float4 r0 = sPool[tid];
        float4 r1 = sPool[tid + 64];
        float4 r2 = sPool[tid + 128];
        float4 r3 = sPool[tid + 192];
        r0.x += r1.x + r2.x + r3.x;
        r0.y += r1.y + r2.y + r3.y;
        r0.z += r1.z + r2.z + r3.z;
        r0.w += r1.w + r2.w + r3.w;
        ((float4*)d_pooled)[(size_t)s * 64 + tid] = r0;
    }
    if (tid == 0) d_gsum[s] = sBC[1];
}

// ---------------------------------------------------------------------------
// Kernel 3: out[S,256] = pooled[S,256] @ Wm[256,256] + gsum[s] * bm
// fp32 SIMT GEMM, 64x64 tile, BK=16, 256 threads, 4x4 microtile.
// ---------------------------------------------------------------------------
#define BM 64
#define BN 64
#define BK 16

__global__ __launch_bounds__(256) void gemm_kernel(
    const float* __restrict__ Wm,   // [256,256] row-major
    const float* __restrict__ bm,   // [256]
    float* __restrict__ out,        // [S,256]
    int S)
{
    __shared__ float As[BK][BM];   // A transposed: As[k][r]
    __shared__ float Bs[BK][BN];

    const int tid = threadIdx.x;
    const int tx = tid & 15, ty = tid >> 4;
    const int m0 = blockIdx.x * BM;
    const int n0 = blockIdx.y * BN;

    // load mappings
    const int ar = tid >> 2;              // A row within tile (0..63)
    const int ak = (tid & 3) * 4;         // A k offset (0..12)
    const int bk = tid >> 4;              // B k row (0..15)
    const int bc = (tid & 15) * 4;        // B col offset (0..60)

    float acc[4][4] = {};

    for (int kb = 0; kb < 256; kb += BK) {
        float4 av = make_float4(0.f, 0.f, 0.f, 0.f);
        if (m0 + ar < S)
            av = *(const float4*)&d_pooled[(size_t)(m0 + ar) * 256 + kb + ak];
        float4 bv = *(const float4*)&Wm[(size_t)(kb + bk) * 256 + n0 + bc];

        __syncthreads();
        As[ak + 0][ar] = av.x;
        As[ak + 1][ar] = av.y;
        As[ak + 2][ar] = av.z;
        As[ak + 3][ar] = av.w;
        *(float4*)&Bs[bk][bc] = bv;
        __syncthreads();

        #pragma unroll
        for (int k = 0; k < BK; k++) {
            float4 a = *(float4*)&As[k][ty * 4];
            float4 b = *(float4*)&Bs[k][tx * 4];
            acc[0][0] += a.x * b.x; acc[0][1] += a.x * b.y; acc[0][2] += a.x * b.z; acc[0][3] += a.x * b.w;
            acc[1][0] += a.y * b.x; acc[1][1] += a.y * b.y; acc[1][2] += a.y * b.z; acc[1][3] += a.y * b.w;
            acc[2][0] += a.z * b.x; acc[2][1] += a.z * b.y; acc[2][2] += a.z * b.z; acc[2][3] += a.z * b.w;
            acc[3][0] += a.w * b.x; acc[3][1] += a.w * b.y; acc[3][2] += a.w * b.z; acc[3][3] += a.w * b.w;
        }
    }

    float4 bmv = *(const float4*)&bm[n0 + tx * 4];
    #pragma unroll
    for (int i = 0; i < 4; i++) {
        int r = m0 + ty * 4 + i;
        if (r < S) {
            float g = d_gsum[r];
            float4 o;
            o.x = acc[i][0] + g * bmv.x;
            o.y = acc[i][1] + g * bmv.y;
            o.z = acc[i][2] + g * bmv.z;
            o.w = acc[i][3] + g * bmv.w;
            *(float4*)&out[(size_t)r * 256 + n0 + tx * 4] = o;
        }
    }
}

// ---------------------------------------------------------------------------
// Inputs (metadata order): x, weights, Wg, bg, Wm, bm, p, index, num_segments
// ---------------------------------------------------------------------------
extern "C" void kernel_launch(void* const* d_in, const int* in_sizes, int n_in,
                              void* d_out, int out_size) {
    const float* x     = (const float*)d_in[0];
    const float* wts   = (const float*)d_in[1];
    const float* Wg    = (const float*)d_in[2];
    const float* bg    = (const float*)d_in[3];
    const float* Wm    = (const float*)d_in[4];
    const float* bm    = (const float*)d_in[5];
    const float* p     = (const float*)d_in[6];
    const int*   index = (const int*)d_in[7];

    const int N = in_sizes[7];        // index element count
    const int S = out_size / 256;     // output rows

    seg_start_kernel<<<(S + 1 + 255) / 256, 256>>>(index, N, S);
    pool_kernel<<<S, 256>>>(x, wts, Wg, bg, p);
    gemm_kernel<<<dim3((S + BM - 1) / BM, 256 / BN), 256>>>(Wm, bm, (float*)d_out, S);
}

// round 2
// speedup vs baseline: 1.0258x; 1.0258x over previous
#include <cuda_runtime.h>
#include <cuda_bf16.h>
#include <math.h>

#define MAXS 24576

__device__ int   d_segstart[MAXS + 1];
__device__ float d_gsum[MAXS];
__device__ float d_pooled[(size_t)MAXS * 256];

// ---------------------------------------------------------------------------
// Kernel 1: segment boundaries by linear scan (index sorted).
// ---------------------------------------------------------------------------
__global__ void seg_bounds_kernel(const int* __restrict__ index, int N, int S) {
    int n = blockIdx.x * blockDim.x + threadIdx.x;
    if (n >= N) return;
    int cur  = index[n];
    int prev = (n == 0) ? -1 : index[n - 1];
    for (int s = prev + 1; s <= cur; s++) d_segstart[s] = n;
    if (n == N - 1)
        for (int s = cur + 1; s <= S; s++) d_segstart[s] = N;
}

// ---------------------------------------------------------------------------
// Kernel 2: fused pooling with online softmax. One block per segment.
// x rows staged through shared memory once (single DRAM pass over x).
// ---------------------------------------------------------------------------
#define CHUNK 32

__global__ __launch_bounds__(256) void pool_kernel(
    const float* __restrict__ x,     // [N,256]
    const float* __restrict__ wts,   // [N]
    const float* __restrict__ Wg,    // [256]
    const float* __restrict__ bg,    // [1]
    const float* __restrict__ p)     // [1]
{
    __shared__ float  xs[CHUNK][256];
    __shared__ float4 sWg4[64];
    __shared__ float  sLog[CHUNK];
    __shared__ float  sE[CHUNK];
    __shared__ float  sRed[8];
    __shared__ float  sSum;

    const int s   = blockIdx.x;
    const int tid = threadIdx.x;
    const int warp = tid >> 5, lane = tid & 31;
    const int beg = d_segstart[s];
    const int cnt = d_segstart[s + 1] - beg;

    if (tid < 64) sWg4[tid] = ((const float4*)Wg)[tid];
    const float bg0 = bg[0];
    const float p0  = p[0];

    float m = -INFINITY, den = 0.0f, acc = 0.0f;
    const float4* __restrict__ x4 = (const float4*)x;

    for (int off = 0; off < cnt; off += CHUNK) {
        const int c = min(CHUNK, cnt - off);
        __syncthreads();   // xs reuse + sWg visibility (first iter)

        // stage chunk rows into smem (coalesced float4)
        for (int idx = tid; idx < c * 64; idx += 256) {
            int r = idx >> 6, col = idx & 63;
            ((float4*)xs[r])[col] = x4[(size_t)(beg + off + r) * 64 + col];
        }
        __syncthreads();

        // logits: one warp per row
        float wmax = -INFINITY;
        for (int i = warp; i < c; i += 8) {
            const float4* row = (const float4*)xs[i];
            float4 a = row[lane];
            float4 b = row[lane + 32];
            float4 ga = sWg4[lane];
            float4 gb = sWg4[lane + 32];
            float sum = a.x*ga.x + a.y*ga.y + a.z*ga.z + a.w*ga.w
                      + b.x*gb.x + b.y*gb.y + b.z*gb.z + b.w*gb.w;
            #pragma unroll
            for (int o = 16; o; o >>= 1)
                sum += __shfl_xor_sync(0xffffffffu, sum, o);
            if (lane == 0) {
                float lg = sum + bg0;
                sLog[i] = lg;
                wmax = fmaxf(wmax, lg);
            }
        }
        if (lane == 0) sRed[warp] = wmax;
        __syncthreads();

        float cm = sRed[0];
        #pragma unroll
        for (int i = 1; i < 8; i++) cm = fmaxf(cm, sRed[i]);
        const float nm    = fmaxf(m, cm);
        const float scale = expf(m - nm);   // first chunk: exp(-inf)=0

        // gates for this chunk (warp 0)
        if (warp == 0) {
            float e = 0.0f;
            if (lane < c)
                e = powf(wts[beg + off + lane], p0) * expf(sLog[lane] - nm);
            sE[lane] = e;
            float ps = e;
            #pragma unroll
            for (int o = 16; o; o >>= 1)
                ps += __shfl_xor_sync(0xffffffffu, ps, o);
            if (lane == 0) sSum = ps;
        }
        __syncthreads();

        den = den * scale + sSum;
        m = nm;

        // accumulate weighted sum: thread owns feature `tid`
        float a2 = acc * scale;
        for (int i = 0; i < c; i++)
            a2 = fmaf(sE[i], xs[i][tid], a2);
        acc = a2;
    }

    const float inv = 1.0f / (den + 1e-10f);
    d_pooled[(size_t)s * 256 + tid] = acc * inv;
    if (tid == 0) d_gsum[s] = den * inv;
}

// ---------------------------------------------------------------------------
// Kernel 3: out = pooled @ Wm + gsum*bm via bf16 split-precision HMMA.
// D = Ah*Bh + Ah*Bl + Al*Bh   (Xh = bf16(X), Xl = bf16(X - Xh))
// Block tile 128x64, 8 warps (2x4), warp tile 64x16, k-step 32.
// ---------------------------------------------------------------------------
#define GM 128
#define GN 64
#define GK 32
#define AK 40    // bf16 elems per A smem row (32 + 8 pad) -> conflict-free frags
#define BNP 68   // fp32 elems per B smem row (64 + 4 pad)

#define MMA_BF16(d, a, b)                                                     \
    asm volatile(                                                             \
        "mma.sync.aligned.m16n8k16.row.col.f32.bf16.bf16.f32 "                \
        "{%0,%1,%2,%3}, {%4,%5,%6,%7}, {%8,%9}, {%0,%1,%2,%3};"               \
        : "+f"((d)[0]), "+f"((d)[1]), "+f"((d)[2]), "+f"((d)[3])              \
        : "r"((a)[0]), "r"((a)[1]), "r"((a)[2]), "r"((a)[3]),                 \
          "r"((b)[0]), "r"((b)[1]))

__device__ __forceinline__ unsigned bf2_to_u32(__nv_bfloat162 v) {
    unsigned u;
    memcpy(&u, &v, 4);
    return u;
}

__global__ __launch_bounds__(256) void gemm_mma_kernel(
    const float* __restrict__ Wm,   // [256,256] row-major
    const float* __restrict__ bm,   // [256]
    float* __restrict__ out,        // [S,256]
    int S)
{
    __shared__ __nv_bfloat16 sAh[GM * AK];
    __shared__ __nv_bfloat16 sAl[GM * AK];
    __shared__ float         sB[GK * BNP];

    const int tid  = threadIdx.x;
    const int warp = tid >> 5, lane = tid & 31;
    const int g = lane >> 2, t = lane & 3;
    const int wm = warp >> 2;          // 0..1  (M)
    const int wn = warp & 3;           // 0..3  (N)
    const int m0 = blockIdx.x * GM;
    const int n0 = blockIdx.y * GN;

    float acc[4][2][4];
    #pragma unroll
    for (int i = 0; i < 4; i++)
        #pragma unroll
        for (int j = 0; j < 2; j++)
            #pragma unroll
            for (int r = 0; r < 4; r++) acc[i][j][r] = 0.0f;

    // loader mappings
    const int lr = tid >> 1;            // A row 0..127
    const int lk = (tid & 1) * 16;      // A k half
    const int bkr = tid >> 3;           // B k row 0..31
    const int bns = (tid & 7) * 8;      // B n seg

    for (int kb = 0; kb < 256; kb += GK) {
        if (kb) __syncthreads();

        // ---- stage A (pooled) as hi/lo bf16 tiles ----
        {
            const int mrow = m0 + lr;
            #pragma unroll
            for (int j = 0; j < 4; j++) {
                float4 v = make_float4(0.f, 0.f, 0.f, 0.f);
                if (mrow < S)
                    v = *(const float4*)&d_pooled[(size_t)mrow * 256 + kb + lk + 4 * j];
                __nv_bfloat162 h0 = __floats2bfloat162_rn(v.x, v.y);
                __nv_bfloat162 h1 = __floats2bfloat162_rn(v.z, v.w);
                __nv_bfloat162 l0 = __floats2bfloat162_rn(v.x - __bfloat162float(h0.x),
                                                          v.y - __bfloat162float(h0.y));
                __nv_bfloat162 l1 = __floats2bfloat162_rn(v.z - __bfloat162float(h1.x),
                                                          v.w - __bfloat162float(h1.y));
                int base = lr * AK + lk + 4 * j;
                *(__nv_bfloat162*)&sAh[base]     = h0;
                *(__nv_bfloat162*)&sAh[base + 2] = h1;
                *(__nv_bfloat162*)&sAl[base]     = l0;
                *(__nv_bfloat162*)&sAl[base + 2] = l1;
            }
        }
        // ---- stage B (Wm) as fp32 tile ----
        {
            #pragma unroll
            for (int j = 0; j < 2; j++) {
                float4 v = *(const float4*)&Wm[(size_t)(kb + bkr) * 256 + n0 + bns + 4 * j];
                *(float4*)&sB[bkr * BNP + bns + 4 * j] = v;
            }
        }
        __syncthreads();

        #pragma unroll
        for (int kk = 0; kk < 2; kk++) {
            const int k16 = kk * 16;

            // B fragments (hi + lo), built from fp32 smem
            unsigned bh[2][2], bl[2][2];
            #pragma unroll
            for (int j = 0; j < 2; j++) {
                const int n = wn * 16 + j * 8 + g;
                float f0 = sB[(k16 + 2 * t    ) * BNP + n];
                float f1 = sB[(k16 + 2 * t + 1) * BNP + n];
                float f2 = sB[(k16 + 2 * t + 8) * BNP + n];
                float f3 = sB[(k16 + 2 * t + 9) * BNP + n];
                __nv_bfloat162 h01 = __floats2bfloat162_rn(f0, f1);
                __nv_bfloat162 h23 = __floats2bfloat162_rn(f2, f3);
                __nv_bfloat162 l01 = __floats2bfloat162_rn(f0 - __bfloat162float(h01.x),
                                                           f1 - __bfloat162float(h01.y));
                __nv_bfloat162 l23 = __floats2bfloat162_rn(f2 - __bfloat162float(h23.x),
                                                           f3 - __bfloat162float(h23.y));
                bh[j][0] = bf2_to_u32(h01); bh[j][1] = bf2_to_u32(h23);
                bl[j][0] = bf2_to_u32(l01); bl[j][1] = bf2_to_u32(l23);
            }

            // A fragments (hi + lo) straight from bf16 smem
            unsigned ah[4][4], al[4][4];
            #pragma unroll
            for (int i = 0; i < 4; i++) {
                const int r = wm * 64 + i * 16;
                int o0 = (r + g    ) * AK + k16 + 2 * t;
                int o1 = (r + g + 8) * AK + k16 + 2 * t;
                ah[i][0] = *(unsigned*)&sAh[o0];
                ah[i][1] = *(unsigned*)&sAh[o1];
                ah[i][2] = *(unsigned*)&sAh[o0 + 8];
                ah[i][3] = *(unsigned*)&sAh[o1 + 8];
                al[i][0] = *(unsigned*)&sAl[o0];
                al[i][1] = *(unsigned*)&sAl[o1];
                al[i][2] = *(unsigned*)&sAl[o0 + 8];
                al[i][3] = *(unsigned*)&sAl[o1 + 8];
            }

            #pragma unroll
            for (int i = 0; i < 4; i++)
                #pragma unroll
                for (int j = 0; j < 2; j++) {
                    MMA_BF16(acc[i][j], ah[i], bh[j]);
                    MMA_BF16(acc[i][j], ah[i], bl[j]);
                    MMA_BF16(acc[i][j], al[i], bh[j]);
                }
        }
    }

    // epilogue: + gsum[m]*bm[n]
    #pragma unroll
    for (int i = 0; i < 4; i++) {
        #pragma unroll
        for (int rr = 0; rr < 2; rr++) {
            const int mrow = m0 + wm * 64 + i * 16 + g + rr * 8;
            if (mrow < S) {
                const float gs = d_gsum[mrow];
                #pragma unroll
                for (int j = 0; j < 2; j++) {
                    const int n = n0 + wn * 16 + j * 8 + 2 * t;
                    float2 o;
                    o.x = acc[i][j][rr * 2 + 0] + gs * bm[n];
                    o.y = acc[i][j][rr * 2 + 1] + gs * bm[n + 1];
                    *(float2*)&out[(size_t)mrow * 256 + n] = o;
                }
            }
        }
    }
}

// ---------------------------------------------------------------------------
// Inputs: x, weights, Wg, bg, Wm, bm, p, index, num_segments
// ---------------------------------------------------------------------------
extern "C" void kernel_launch(void* const* d_in, const int* in_sizes, int n_in,
                              void* d_out, int out_size) {
    const float* x     = (const float*)d_in[0];
    const float* wts   = (const float*)d_in[1];
    const float* Wg    = (const float*)d_in[2];
    const float* bg    = (const float*)d_in[3];
    const float* Wm    = (const float*)d_in[4];
    const float* bm    = (const float*)d_in[5];
    const float* p     = (const float*)d_in[6];
    const int*   index = (const int*)d_in[7];

    const int N = in_sizes[7];
    const int S = out_size / 256;

    seg_bounds_kernel<<<(N + 255) / 256, 256>>>(index, N, S);
    pool_kernel<<<S, 256>>>(x, wts, Wg, bg, p);
    gemm_mma_kernel<<<dim3((S + GM - 1) / GM, 256 / GN), 256>>>(Wm, bm, (float*)d_out, S);
}

// round 3
// speedup vs baseline: 1.3333x; 1.2997x over previous
#include <cuda_runtime.h>
#include <cuda_bf16.h>
#include <math.h>

#define MAXS 24576

__device__ int   d_segstart[MAXS + 1];
__device__ float d_gsum[MAXS];
__device__ __nv_bfloat16 d_ph[(size_t)MAXS * 256];   // pooled hi (bf16 split)
__device__ __nv_bfloat16 d_pl[(size_t)MAXS * 256];   // pooled lo
__device__ __nv_bfloat16 d_Wth[256 * 256];           // Wm^T hi  [n][k]
__device__ __nv_bfloat16 d_Wtl[256 * 256];           // Wm^T lo

__device__ __forceinline__ float ex2f(float x) {
    float y; asm("ex2.approx.ftz.f32 %0, %1;" : "=f"(y) : "f"(x)); return y;
}
__device__ __forceinline__ float lg2f(float x) {
    float y; asm("lg2.approx.ftz.f32 %0, %1;" : "=f"(y) : "f"(x)); return y;
}
#define L2E 1.4426950408889634f

// ---------------------------------------------------------------------------
// Kernel 1: segment boundaries (index sorted), 4 nodes per thread.
// ---------------------------------------------------------------------------
__global__ void seg_bounds_kernel(const int* __restrict__ index, int N, int S) {
    int base = (blockIdx.x * blockDim.x + threadIdx.x) * 4;
    if (base >= N) return;
    int prev = (base == 0) ? -1 : index[base - 1];
    int v[4];
    if (base + 3 < N) {
        int4 q = *(const int4*)&index[base];
        v[0] = q.x; v[1] = q.y; v[2] = q.z; v[3] = q.w;
    } else {
        for (int k = 0; k < 4; k++) v[k] = (base + k < N) ? index[base + k] : 0;
    }
    #pragma unroll
    for (int k = 0; k < 4; k++) {
        int n = base + k;
        if (n < N) {
            for (int s = prev + 1; s <= v[k]; s++) d_segstart[s] = n;
            prev = v[k];
            if (n == N - 1)
                for (int s = v[k] + 1; s <= S; s++) d_segstart[s] = N;
        }
    }
}

// ---------------------------------------------------------------------------
// Kernel 2: prep — transpose + bf16-split Wm into Wt[n][k] (hi/lo).
// ---------------------------------------------------------------------------
__global__ void prep_kernel(const float* __restrict__ Wm) {
    __shared__ float tile[32][33];
    const int k0 = blockIdx.y * 32, n0 = blockIdx.x * 32;
    for (int r = threadIdx.y; r < 32; r += 8)
        tile[r][threadIdx.x] = Wm[(size_t)(k0 + r) * 256 + n0 + threadIdx.x];
    __syncthreads();
    for (int r = threadIdx.y; r < 32; r += 8) {
        float v = tile[threadIdx.x][r];               // Wm[k0+tx][n0+r]
        __nv_bfloat16 h = __float2bfloat16(v);
        __nv_bfloat16 l = __float2bfloat16(v - __bfloat162float(h));
        size_t o = (size_t)(n0 + r) * 256 + k0 + threadIdx.x;
        d_Wth[o] = h;
        d_Wtl[o] = l;
    }
}

// ---------------------------------------------------------------------------
// Kernel 3: pooling — ONE WARP PER SEGMENT, no smem, no block syncs.
// Online softmax; Wg and the 256-wide accumulator live in registers
// (8 floats per lane). Single DRAM pass over x. Output: split bf16 pooled.
// ---------------------------------------------------------------------------
__global__ __launch_bounds__(256) void pool_kernel(
    const float* __restrict__ x,     // [N,256]
    const float* __restrict__ wts,   // [N]
    const float* __restrict__ Wg,    // [256]
    const float* __restrict__ bg,
    const float* __restrict__ p,
    int S)
{
    const int s = blockIdx.x * 8 + (threadIdx.x >> 5);
    if (s >= S) return;
    const int lane = threadIdx.x & 31;

    const float4* __restrict__ x4 = (const float4*)x;
    const float4 wg0 = ((const float4*)Wg)[lane];
    const float4 wg1 = ((const float4*)Wg)[lane + 32];
    const float bg0 = bg[0];
    const float p0  = p[0];

    const int beg = d_segstart[s];
    const int cnt = d_segstart[s + 1] - beg;

    float4 a0 = make_float4(0.f, 0.f, 0.f, 0.f);
    float4 a1 = make_float4(0.f, 0.f, 0.f, 0.f);
    float m = -INFINITY, den = 0.0f;

    float4 c0 = make_float4(0.f, 0.f, 0.f, 0.f);
    float4 c1 = make_float4(0.f, 0.f, 0.f, 0.f);
    float cw = 1.0f;
    if (cnt > 0) {
        size_t b = (size_t)beg * 64;
        c0 = x4[b + lane];
        c1 = x4[b + 32 + lane];
        cw = wts[beg];
    }

    for (int i = 0; i < cnt; i++) {
        // prefetch next row
        float4 n0v = make_float4(0.f, 0.f, 0.f, 0.f);
        float4 n1v = make_float4(0.f, 0.f, 0.f, 0.f);
        float nw = 1.0f;
        if (i + 1 < cnt) {
            size_t b = (size_t)(beg + i + 1) * 64;
            n0v = x4[b + lane];
            n1v = x4[b + 32 + lane];
            nw = wts[beg + i + 1];
        }

        // logit = dot(x_row, Wg) + bg
        float dot = c0.x * wg0.x + c0.y * wg0.y + c0.z * wg0.z + c0.w * wg0.w
                  + c1.x * wg1.x + c1.y * wg1.y + c1.z * wg1.z + c1.w * wg1.w;
        #pragma unroll
        for (int o = 16; o; o >>= 1)
            dot += __shfl_xor_sync(0xffffffffu, dot, o);
        const float lg = dot + bg0;

        const float nm = fmaxf(m, lg);
        const float sc = ex2f((m - nm) * L2E);      // first row: ex2(-inf)=0
        const float e  = ex2f(fmaf(p0, lg2f(cw), (lg - nm) * L2E));
        den = den * sc + e;
        a0.x = fmaf(e, c0.x, a0.x * sc);
        a0.y = fmaf(e, c0.y, a0.y * sc);
        a0.z = fmaf(e, c0.z, a0.z * sc);
        a0.w = fmaf(e, c0.w, a0.w * sc);
        a1.x = fmaf(e, c1.x, a1.x * sc);
        a1.y = fmaf(e, c1.y, a1.y * sc);
        a1.z = fmaf(e, c1.z, a1.z * sc);
        a1.w = fmaf(e, c1.w, a1.w * sc);
        m = nm;

        c0 = n0v; c1 = n1v; cw = nw;
    }

    const float inv = 1.0f / (den + 1e-10f);
    float4 r0, r1;
    r0.x = a0.x * inv; r0.y = a0.y * inv; r0.z = a0.z * inv; r0.w = a0.w * inv;
    r1.x = a1.x * inv; r1.y = a1.y * inv; r1.z = a1.z * inv; r1.w = a1.w * inv;

    // split into bf16 hi/lo and store (8B per lane per half)
    {
        __nv_bfloat162 h01 = __floats2bfloat162_rn(r0.x, r0.y);
        __nv_bfloat162 h23 = __floats2bfloat162_rn(r0.z, r0.w);
        __nv_bfloat162 l01 = __floats2bfloat162_rn(r0.x - __bfloat162float(h01.x),
                                                   r0.y - __bfloat162float(h01.y));
        __nv_bfloat162 l23 = __floats2bfloat162_rn(r0.z - __bfloat162float(h23.x),
                                                   r0.w - __bfloat162float(h23.y));
        size_t o = (size_t)s * 256 + 4 * lane;
        uint2 uh, ul;
        memcpy(&uh.x, &h01, 4); memcpy(&uh.y, &h23, 4);
        memcpy(&ul.x, &l01, 4); memcpy(&ul.y, &l23, 4);
        *(uint2*)&d_ph[o] = uh;
        *(uint2*)&d_pl[o] = ul;
    }
    {
        __nv_bfloat162 h01 = __floats2bfloat162_rn(r1.x, r1.y);
        __nv_bfloat162 h23 = __floats2bfloat162_rn(r1.z, r1.w);
        __nv_bfloat162 l01 = __floats2bfloat162_rn(r1.x - __bfloat162float(h01.x),
                                                   r1.y - __bfloat162float(h01.y));
        __nv_bfloat162 l23 = __floats2bfloat162_rn(r1.z - __bfloat162float(h23.x),
                                                   r1.w - __bfloat162float(h23.y));
        size_t o = (size_t)s * 256 + 128 + 4 * lane;
        uint2 uh, ul;
        memcpy(&uh.x, &h01, 4); memcpy(&uh.y, &h23, 4);
        memcpy(&ul.x, &l01, 4); memcpy(&ul.y, &l23, 4);
        *(uint2*)&d_ph[o] = uh;
        *(uint2*)&d_pl[o] = ul;
    }
    if (lane == 0) d_gsum[s] = den * inv;
}

// ---------------------------------------------------------------------------
// Kernel 4: out = pooled @ Wm + gsum*bm, split-bf16 HMMA (3-term).
// Operands pre-split in bf16; mainloop has zero conversions.
// ---------------------------------------------------------------------------
#define GM 128
#define GN 64
#define GK 32
#define AK 40   // bf16 per smem row (32 + 8 pad)

#define MMA_BF16(d, a, b)                                                     \
    asm volatile(                                                             \
        "mma.sync.aligned.m16n8k16.row.col.f32.bf16.bf16.f32 "                \
        "{%0,%1,%2,%3}, {%4,%5,%6,%7}, {%8,%9}, {%0,%1,%2,%3};"               \
        : "+f"((d)[0]), "+f"((d)[1]), "+f"((d)[2]), "+f"((d)[3])              \
        : "r"((a)[0]), "r"((a)[1]), "r"((a)[2]), "r"((a)[3]),                 \
          "r"((b)[0]), "r"((b)[1]))

__global__ __launch_bounds__(256) void gemm_mma_kernel(
    const float* __restrict__ bm,
    float* __restrict__ out,
    int S)
{
    __shared__ __nv_bfloat16 sAh[GM * AK];
    __shared__ __nv_bfloat16 sAl[GM * AK];
    __shared__ __nv_bfloat16 sBh[GN * AK];
    __shared__ __nv_bfloat16 sBl[GN * AK];

    const int tid  = threadIdx.x;
    const int warp = tid >> 5, lane = tid & 31;
    const int g = lane >> 2, t = lane & 3;
    const int wm = warp >> 2;          // 0..1
    const int wn = warp & 3;           // 0..3
    const int m0 = blockIdx.x * GM;
    const int n0 = blockIdx.y * GN;

    float acc[4][2][4] = {};

    // loader mappings
    const int lr  = tid >> 1;             // A row 0..127
    const int lk  = (tid & 1) * 16;       // A k half
    const int bn  = tid >> 2;             // B row (n) 0..63
    const int bk8 = (tid & 3) * 8;        // B k oct

    for (int kb = 0; kb < 256; kb += GK) {
        if (kb) __syncthreads();

        // stage A (pre-split bf16)
        {
            const int mrow = m0 + lr;
            #pragma unroll
            for (int j = 0; j < 2; j++) {
                uint4 vh = make_uint4(0, 0, 0, 0), vl = make_uint4(0, 0, 0, 0);
                if (mrow < S) {
                    size_t o = (size_t)mrow * 256 + kb + lk + 8 * j;
                    vh = *(const uint4*)&d_ph[o];
                    vl = *(const uint4*)&d_pl[o];
                }
                int sbase = lr * AK + lk + 8 * j;
                *(uint4*)&sAh[sbase] = vh;
                *(uint4*)&sAl[sbase] = vl;
            }
        }
        // stage B (pre-split, pre-transposed bf16)
        {
            size_t o = (size_t)(n0 + bn) * 256 + kb + bk8;
            *(uint4*)&sBh[bn * AK + bk8] = *(const uint4*)&d_Wth[o];
            *(uint4*)&sBl[bn * AK + bk8] = *(const uint4*)&d_Wtl[o];
        }
        __syncthreads();

        #pragma unroll
        for (int kk = 0; kk < 2; kk++) {
            const int k16 = kk * 16;

            unsigned bh[2][2], bl[2][2];
            #pragma unroll
            for (int j = 0; j < 2; j++) {
                const int n = wn * 16 + j * 8 + g;
                bh[j][0] = *(unsigned*)&sBh[n * AK + k16 + 2 * t];
                bh[j][1] = *(unsigned*)&sBh[n * AK + k16 + 2 * t + 8];
                bl[j][0] = *(unsigned*)&sBl[n * AK + k16 + 2 * t];
                bl[j][1] = *(unsigned*)&sBl[n * AK + k16 + 2 * t + 8];
            }

            unsigned ah[4][4], al[4][4];
            #pragma unroll
            for (int i = 0; i < 4; i++) {
                const int r = wm * 64 + i * 16;
                int o0 = (r + g    ) * AK + k16 + 2 * t;
                int o1 = (r + g + 8) * AK + k16 + 2 * t;
                ah[i][0] = *(unsigned*)&sAh[o0];
                ah[i][1] = *(unsigned*)&sAh[o1];
                ah[i][2] = *(unsigned*)&sAh[o0 + 8];
                ah[i][3] = *(unsigned*)&sAh[o1 + 8];
                al[i][0] = *(unsigned*)&sAl[o0];
                al[i][1] = *(unsigned*)&sAl[o1];
                al[i][2] = *(unsigned*)&sAl[o0 + 8];
                al[i][3] = *(unsigned*)&sAl[o1 + 8];
            }

            #pragma unroll
            for (int i = 0; i < 4; i++)
                #pragma unroll
                for (int j = 0; j < 2; j++) {
                    MMA_BF16(acc[i][j], ah[i], bh[j]);
                    MMA_BF16(acc[i][j], ah[i], bl[j]);
                    MMA_BF16(acc[i][j], al[i], bh[j]);
                }
        }
    }

    #pragma unroll
    for (int i = 0; i < 4; i++) {
        #pragma unroll
        for (int rr = 0; rr < 2; rr++) {
            const int mrow = m0 + wm * 64 + i * 16 + g + rr * 8;
            if (mrow < S) {
                const float gs = d_gsum[mrow];
                #pragma unroll
                for (int j = 0; j < 2; j++) {
                    const int n = n0 + wn * 16 + j * 8 + 2 * t;
                    float2 o;
                    o.x = acc[i][j][rr * 2 + 0] + gs * bm[n];
                    o.y = acc[i][j][rr * 2 + 1] + gs * bm[n + 1];
                    *(float2*)&out[(size_t)mrow * 256 + n] = o;
                }
            }
        }
    }
}

// ---------------------------------------------------------------------------
// Inputs: x, weights, Wg, bg, Wm, bm, p, index, num_segments
// ---------------------------------------------------------------------------
extern "C" void kernel_launch(void* const* d_in, const int* in_sizes, int n_in,
                              void* d_out, int out_size) {
    const float* x     = (const float*)d_in[0];
    const float* wts   = (const float*)d_in[1];
    const float* Wg    = (const float*)d_in[2];
    const float* bg    = (const float*)d_in[3];
    const float* Wm    = (const float*)d_in[4];
    const float* bm    = (const float*)d_in[5];
    const float* p     = (const float*)d_in[6];
    const int*   index = (const int*)d_in[7];

    const int N = in_sizes[7];
    const int S = out_size / 256;

    seg_bounds_kernel<<<(N / 4 + 256) / 256, 256>>>(index, N, S);
    prep_kernel<<<dim3(8, 8), dim3(32, 8)>>>(Wm);
    pool_kernel<<<(S + 7) / 8, 256>>>(x, wts, Wg, bg, p, S);
    gemm_mma_kernel<<<dim3((S + GM - 1) / GM, 256 / GN), 256>>>(bm, (float*)d_out, S);
}

// round 4
// speedup vs baseline: 1.4455x; 1.0842x over previous
#include <cuda_runtime.h>
#include <cuda_bf16.h>
#include <math.h>

#define MAXS 24576

__device__ int   d_segstart[MAXS + 1];
__device__ float d_gsum[MAXS];
__device__ __nv_bfloat16 d_ph[(size_t)MAXS * 256];   // pooled hi (bf16 split)
__device__ __nv_bfloat16 d_pl[(size_t)MAXS * 256];   // pooled lo
__device__ __nv_bfloat16 d_Wth[256 * 256];           // Wm^T hi  [n][k]
__device__ __nv_bfloat16 d_Wtl[256 * 256];           // Wm^T lo

__device__ __forceinline__ float ex2f(float x) {
    float y; asm("ex2.approx.ftz.f32 %0, %1;" : "=f"(y) : "f"(x)); return y;
}
__device__ __forceinline__ float lg2f(float x) {
    float y; asm("lg2.approx.ftz.f32 %0, %1;" : "=f"(y) : "f"(x)); return y;
}
#define L2E 1.4426950408889634f

// ---------------------------------------------------------------------------
// Kernel 1: segment boundaries (index sorted), 4 nodes per thread.
// ---------------------------------------------------------------------------
__global__ void seg_bounds_kernel(const int* __restrict__ index, int N, int S) {
    int base = (blockIdx.x * blockDim.x + threadIdx.x) * 4;
    if (base >= N) return;
    int prev = (base == 0) ? -1 : index[base - 1];
    int v[4];
    if (base + 3 < N) {
        int4 q = *(const int4*)&index[base];
        v[0] = q.x; v[1] = q.y; v[2] = q.z; v[3] = q.w;
    } else {
        for (int k = 0; k < 4; k++) v[k] = (base + k < N) ? index[base + k] : 0;
    }
    #pragma unroll
    for (int k = 0; k < 4; k++) {
        int n = base + k;
        if (n < N) {
            for (int s = prev + 1; s <= v[k]; s++) d_segstart[s] = n;
            prev = v[k];
            if (n == N - 1)
                for (int s = v[k] + 1; s <= S; s++) d_segstart[s] = N;
        }
    }
}

// ---------------------------------------------------------------------------
// Kernel 2: prep — transpose + bf16-split Wm into Wt[n][k] (hi/lo).
// ---------------------------------------------------------------------------
__global__ void prep_kernel(const float* __restrict__ Wm) {
    __shared__ float tile[32][33];
    const int k0 = blockIdx.y * 32, n0 = blockIdx.x * 32;
    for (int r = threadIdx.y; r < 32; r += 8)
        tile[r][threadIdx.x] = Wm[(size_t)(k0 + r) * 256 + n0 + threadIdx.x];
    __syncthreads();
    for (int r = threadIdx.y; r < 32; r += 8) {
        float v = tile[threadIdx.x][r];
        __nv_bfloat16 h = __float2bfloat16(v);
        __nv_bfloat16 l = __float2bfloat16(v - __bfloat162float(h));
        size_t o = (size_t)(n0 + r) * 256 + k0 + threadIdx.x;
        d_Wth[o] = h;
        d_Wtl[o] = l;
    }
}

// ---------------------------------------------------------------------------
// Kernel 3: pooling — one warp per segment, online softmax, registers only.
// ---------------------------------------------------------------------------
__global__ __launch_bounds__(256) void pool_kernel(
    const float* __restrict__ x,
    const float* __restrict__ wts,
    const float* __restrict__ Wg,
    const float* __restrict__ bg,
    const float* __restrict__ p,
    int S)
{
    const int s = blockIdx.x * 8 + (threadIdx.x >> 5);
    if (s >= S) return;
    const int lane = threadIdx.x & 31;

    const float4* __restrict__ x4 = (const float4*)x;
    const float4 wg0 = ((const float4*)Wg)[lane];
    const float4 wg1 = ((const float4*)Wg)[lane + 32];
    const float bg0 = bg[0];
    const float p0  = p[0];

    const int beg = d_segstart[s];
    const int cnt = d_segstart[s + 1] - beg;

    float4 a0 = make_float4(0.f, 0.f, 0.f, 0.f);
    float4 a1 = make_float4(0.f, 0.f, 0.f, 0.f);
    float m = -INFINITY, den = 0.0f;

    float4 c0 = make_float4(0.f, 0.f, 0.f, 0.f);
    float4 c1 = make_float4(0.f, 0.f, 0.f, 0.f);
    float cw = 1.0f;
    if (cnt > 0) {
        size_t b = (size_t)beg * 64;
        c0 = x4[b + lane];
        c1 = x4[b + 32 + lane];
        cw = wts[beg];
    }

    for (int i = 0; i < cnt; i++) {
        float4 n0v = make_float4(0.f, 0.f, 0.f, 0.f);
        float4 n1v = make_float4(0.f, 0.f, 0.f, 0.f);
        float nw = 1.0f;
        if (i + 1 < cnt) {
            size_t b = (size_t)(beg + i + 1) * 64;
            n0v = x4[b + lane];
            n1v = x4[b + 32 + lane];
            nw = wts[beg + i + 1];
        }

        float dot = c0.x * wg0.x + c0.y * wg0.y + c0.z * wg0.z + c0.w * wg0.w
                  + c1.x * wg1.x + c1.y * wg1.y + c1.z * wg1.z + c1.w * wg1.w;
        #pragma unroll
        for (int o = 16; o; o >>= 1)
            dot += __shfl_xor_sync(0xffffffffu, dot, o);
        const float lg = dot + bg0;

        const float nm = fmaxf(m, lg);
        const float sc = ex2f((m - nm) * L2E);
        const float e  = ex2f(fmaf(p0, lg2f(cw), (lg - nm) * L2E));
        den = den * sc + e;
        a0.x = fmaf(e, c0.x, a0.x * sc);
        a0.y = fmaf(e, c0.y, a0.y * sc);
        a0.z = fmaf(e, c0.z, a0.z * sc);
        a0.w = fmaf(e, c0.w, a0.w * sc);
        a1.x = fmaf(e, c1.x, a1.x * sc);
        a1.y = fmaf(e, c1.y, a1.y * sc);
        a1.z = fmaf(e, c1.z, a1.z * sc);
        a1.w = fmaf(e, c1.w, a1.w * sc);
        m = nm;

        c0 = n0v; c1 = n1v; cw = nw;
    }

    const float inv = 1.0f / (den + 1e-10f);
    float4 r0, r1;
    r0.x = a0.x * inv; r0.y = a0.y * inv; r0.z = a0.z * inv; r0.w = a0.w * inv;
    r1.x = a1.x * inv; r1.y = a1.y * inv; r1.z = a1.z * inv; r1.w = a1.w * inv;

    {
        __nv_bfloat162 h01 = __floats2bfloat162_rn(r0.x, r0.y);
        __nv_bfloat162 h23 = __floats2bfloat162_rn(r0.z, r0.w);
        __nv_bfloat162 l01 = __floats2bfloat162_rn(r0.x - __bfloat162float(h01.x),
                                                   r0.y - __bfloat162float(h01.y));
        __nv_bfloat162 l23 = __floats2bfloat162_rn(r0.z - __bfloat162float(h23.x),
                                                   r0.w - __bfloat162float(h23.y));
        size_t o = (size_t)s * 256 + 4 * lane;
        uint2 uh, ul;
        memcpy(&uh.x, &h01, 4); memcpy(&uh.y, &h23, 4);
        memcpy(&ul.x, &l01, 4); memcpy(&ul.y, &l23, 4);
        *(uint2*)&d_ph[o] = uh;
        *(uint2*)&d_pl[o] = ul;
    }
    {
        __nv_bfloat162 h01 = __floats2bfloat162_rn(r1.x, r1.y);
        __nv_bfloat162 h23 = __floats2bfloat162_rn(r1.z, r1.w);
        __nv_bfloat162 l01 = __floats2bfloat162_rn(r1.x - __bfloat162float(h01.x),
                                                   r1.y - __bfloat162float(h01.y));
        __nv_bfloat162 l23 = __floats2bfloat162_rn(r1.z - __bfloat162float(h23.x),
                                                   r1.w - __bfloat162float(h23.y));
        size_t o = (size_t)s * 256 + 128 + 4 * lane;
        uint2 uh, ul;
        memcpy(&uh.x, &h01, 4); memcpy(&uh.y, &h23, 4);
        memcpy(&ul.x, &l01, 4); memcpy(&ul.y, &l23, 4);
        *(uint2*)&d_ph[o] = uh;
        *(uint2*)&d_pl[o] = ul;
    }
    if (lane == 0) d_gsum[s] = den * inv;
}

// ---------------------------------------------------------------------------
// Kernel 4: split-bf16 HMMA GEMM, cp.async double-buffered + ldmatrix.
// Block 128x128 (512 thr, warp grid 4x4, warp tile 32x32), K-step 32.
// ---------------------------------------------------------------------------
#define GM 128
#define GN 128
#define AK 40                   // bf16 per padded smem row
#define TILE_B (128 * AK * 2)   // 10240 bytes per operand tile
#define STAGE_B (4 * TILE_B)    // Ah,Al,Bh,Bl

#define MMA_BF16(d, a, b)                                                     \
    asm volatile(                                                             \
        "mma.sync.aligned.m16n8k16.row.col.f32.bf16.bf16.f32 "                \
        "{%0,%1,%2,%3}, {%4,%5,%6,%7}, {%8,%9}, {%0,%1,%2,%3};"               \
        : "+f"((d)[0]), "+f"((d)[1]), "+f"((d)[2]), "+f"((d)[3])              \
        : "r"((a)[0]), "r"((a)[1]), "r"((a)[2]), "r"((a)[3]),                 \
          "r"((b)[0]), "r"((b)[1]))

__device__ __forceinline__ void ldsm_x4(unsigned& r0, unsigned& r1,
                                        unsigned& r2, unsigned& r3,
                                        unsigned addr) {
    asm volatile("ldmatrix.sync.aligned.m8n8.x4.shared.b16 {%0,%1,%2,%3}, [%4];"
                 : "=r"(r0), "=r"(r1), "=r"(r2), "=r"(r3) : "r"(addr));
}
__device__ __forceinline__ void cp16(unsigned dst, const void* src, int sz) {
    asm volatile("cp.async.cg.shared.global [%0], [%1], 16, %2;"
                 :: "r"(dst), "l"(src), "r"(sz));
}

__global__ __launch_bounds__(512) void gemm_mma_kernel(
    const float* __restrict__ bm,
    float* __restrict__ out,
    int S)
{
    extern __shared__ char smem[];
    const unsigned sbase = (unsigned)__cvta_generic_to_shared(smem);

    const int tid  = threadIdx.x;
    const int warp = tid >> 5, lane = tid & 31;
    const int g = lane >> 2, t = lane & 3;
    const int wm = warp >> 2;          // 0..3 (M)
    const int wn = warp & 3;           // 0..3 (N)
    const int m0 = blockIdx.x * GM;
    const int n0 = blockIdx.y * GN;

    float acc[2][4][4] = {};           // [m16 tile][n8 frag][regs]

    // ---- loader mapping: each thread: 1 chunk each of Ah, Al, Bh, Bl ----
    const int lrow = tid >> 2;         // 0..127
    const int lchk = tid & 3;          // 16B chunk within 64B row
    int asrc_row = m0 + lrow;
    const int asz = (asrc_row < S) ? 16 : 0;
    if (asrc_row >= S) asrc_row = 0;
    const unsigned dst_off = lrow * (AK * 2) + lchk * 16;

    // ---- ldmatrix per-lane invariant offsets (bytes) ----
    // A: rows m (T0-15), k halves (T16-31 at +8 k)
    unsigned a_off[2];
    #pragma unroll
    for (int i = 0; i < 2; i++)
        a_off[i] = (wm * 32 + i * 16 + (lane & 15)) * (AK * 2) + (lane >> 4) * 16;
    // B: rows n, T0-7 n0..7@k0, T8-15 n0..7@k8, T16-23 n8..15@k0, T24-31 n8..15@k8
    unsigned b_off[2];
    #pragma unroll
    for (int j = 0; j < 2; j++)
        b_off[j] = (wn * 32 + j * 16 + ((lane >> 4) << 3) + (lane & 7)) * (AK * 2)
                 + (((lane >> 3) & 1) << 4);

    // ---- async load of one K-stage ----
    auto load_stage = [&](int it) {
        const int kb = it * 32;
        const unsigned sb = sbase + (it & 1) * STAGE_B;
        const size_t ga = (size_t)asrc_row * 256 + kb + lchk * 8;
        const size_t gb = (size_t)(n0 + lrow) * 256 + kb + lchk * 8;
        cp16(sb + dst_off,              &d_ph[ga],  asz);
        cp16(sb + TILE_B + dst_off,     &d_pl[ga],  asz);
        cp16(sb + 2 * TILE_B + dst_off, &d_Wth[gb], 16);
        cp16(sb + 3 * TILE_B + dst_off, &d_Wtl[gb], 16);
        asm volatile("cp.async.commit_group;");
    };

    load_stage(0);
    load_stage(1);

    #pragma unroll
    for (int it = 0; it < 8; it++) {
        if (it < 6) asm volatile("cp.async.wait_group 1;");
        else        asm volatile("cp.async.wait_group 0;");
        __syncthreads();

        const unsigned sb = sbase + (it & 1) * STAGE_B;

        #pragma unroll
        for (int kk = 0; kk < 2; kk++) {
            const unsigned kadd = kk * 32;   // 16 bf16 = 32 bytes

            unsigned ah[2][4], al[2][4];
            #pragma unroll
            for (int i = 0; i < 2; i++) {
                ldsm_x4(ah[i][0], ah[i][1], ah[i][2], ah[i][3],
                        sb + a_off[i] + kadd);
                ldsm_x4(al[i][0], al[i][1], al[i][2], al[i][3],
                        sb + TILE_B + a_off[i] + kadd);
            }
            unsigned bh[4][2], bl[4][2];
            #pragma unroll
            for (int j = 0; j < 2; j++) {
                unsigned r0, r1, r2, r3;
                ldsm_x4(r0, r1, r2, r3, sb + 2 * TILE_B + b_off[j] + kadd);
                bh[2 * j][0] = r0; bh[2 * j][1] = r1;
                bh[2 * j + 1][0] = r2; bh[2 * j + 1][1] = r3;
                ldsm_x4(r0, r1, r2, r3, sb + 3 * TILE_B + b_off[j] + kadd);
                bl[2 * j][0] = r0; bl[2 * j][1] = r1;
                bl[2 * j + 1][0] = r2; bl[2 * j + 1][1] = r3;
            }

            #pragma unroll
            for (int i = 0; i < 2; i++)
                #pragma unroll
                for (int j = 0; j < 4; j++) {
                    MMA_BF16(acc[i][j], ah[i], bh[j]);
                    MMA_BF16(acc[i][j], ah[i], bl[j]);
                    MMA_BF16(acc[i][j], al[i], bh[j]);
                }
        }
        __syncthreads();
        if (it + 2 < 8) load_stage(it + 2);
    }

    // ---- epilogue: + gsum[m] * bm[n] ----
    #pragma unroll
    for (int i = 0; i < 2; i++) {
        #pragma unroll
        for (int rr = 0; rr < 2; rr++) {
            const int mrow = m0 + wm * 32 + i * 16 + g + rr * 8;
            if (mrow < S) {
                const float gs = d_gsum[mrow];
                #pragma unroll
                for (int j = 0; j < 4; j++) {
                    const int n = n0 + wn * 32 + j * 8 + 2 * t;
                    float2 o;
                    o.x = acc[i][j][rr * 2 + 0] + gs * bm[n];
                    o.y = acc[i][j][rr * 2 + 1] + gs * bm[n + 1];
                    *(float2*)&out[(size_t)mrow * 256 + n] = o;
                }
            }
        }
    }
}

// ---------------------------------------------------------------------------
// Inputs: x, weights, Wg, bg, Wm, bm, p, index, num_segments
// ---------------------------------------------------------------------------
extern "C" void kernel_launch(void* const* d_in, const int* in_sizes, int n_in,
                              void* d_out, int out_size) {
    const float* x     = (const float*)d_in[0];
    const float* wts   = (const float*)d_in[1];
    const float* Wg    = (const float*)d_in[2];
    const float* bg    = (const float*)d_in[3];
    const float* Wm    = (const float*)d_in[4];
    const float* bm    = (const float*)d_in[5];
    const float* p     = (const float*)d_in[6];
    const int*   index = (const int*)d_in[7];

    const int N = in_sizes[7];
    const int S = out_size / 256;
    const int smem_bytes = 2 * STAGE_B;   // 81920

    cudaFuncSetAttribute(gemm_mma_kernel,
                         cudaFuncAttributeMaxDynamicSharedMemorySize, smem_bytes);

    seg_bounds_kernel<<<(N / 4 + 256) / 256, 256>>>(index, N, S);
    prep_kernel<<<dim3(8, 8), dim3(32, 8)>>>(Wm);
    pool_kernel<<<(S + 7) / 8, 256>>>(x, wts, Wg, bg, p, S);
    gemm_mma_kernel<<<dim3((S + GM - 1) / GM, 256 / GN), 512, smem_bytes>>>(
        bm, (float*)d_out, S);
}

// round 8
// speedup vs baseline: 1.4722x; 1.0184x over previous
#include <cuda_runtime.h>
#include <cuda_bf16.h>
#include <cstdint>
#include <cstring>
#include <math.h>

#define MAXS 24576

__device__ int   d_segstart[MAXS + 1];
__device__ float d_gsum[MAXS];
__device__ __nv_bfloat16 d_ph[(size_t)MAXS * 256];   // pooled hi (bf16 split)
__device__ __nv_bfloat16 d_pl[(size_t)MAXS * 256];   // pooled lo
__device__ __nv_bfloat16 d_Wth[256 * 256];           // Wm^T hi  [n][k]
__device__ __nv_bfloat16 d_Wtl[256 * 256];           // Wm^T lo

__device__ __forceinline__ float ex2f(float x) {
    float y; asm("ex2.approx.ftz.f32 %0, %1;" : "=f"(y) : "f"(x)); return y;
}
__device__ __forceinline__ float lg2f(float x) {
    float y; asm("lg2.approx.ftz.f32 %0, %1;" : "=f"(y) : "f"(x)); return y;
}
#define L2E 1.4426950408889634f

// ---------------------------------------------------------------------------
// Kernel 1: segment boundaries (index sorted), 4 nodes per thread.
// ---------------------------------------------------------------------------
__global__ void seg_bounds_kernel(const int* __restrict__ index, int N, int S) {
    int base = (blockIdx.x * blockDim.x + threadIdx.x) * 4;
    if (base >= N) return;
    int prev = (base == 0) ? -1 : index[base - 1];
    int v[4];
    if (base + 3 < N) {
        int4 q = *(const int4*)&index[base];
        v[0] = q.x; v[1] = q.y; v[2] = q.z; v[3] = q.w;
    } else {
        for (int k = 0; k < 4; k++) v[k] = (base + k < N) ? index[base + k] : 0;
    }
    #pragma unroll
    for (int k = 0; k < 4; k++) {
        int n = base + k;
        if (n < N) {
            for (int s = prev + 1; s <= v[k]; s++) d_segstart[s] = n;
            prev = v[k];
            if (n == N - 1)
                for (int s = v[k] + 1; s <= S; s++) d_segstart[s] = N;
        }
    }
}

// ---------------------------------------------------------------------------
// Kernel 2: prep — transpose + bf16-split Wm into Wt[n][k] (hi/lo).
// ---------------------------------------------------------------------------
__global__ void prep_kernel(const float* __restrict__ Wm) {
    __shared__ float tile[32][33];
    const int k0 = blockIdx.y * 32, n0 = blockIdx.x * 32;
    for (int r = threadIdx.y; r < 32; r += 8)
        tile[r][threadIdx.x] = Wm[(size_t)(k0 + r) * 256 + n0 + threadIdx.x];
    __syncthreads();
    for (int r = threadIdx.y; r < 32; r += 8) {
        float v = tile[threadIdx.x][r];
        __nv_bfloat16 h = __float2bfloat16(v);
        __nv_bfloat16 l = __float2bfloat16(v - __bfloat162float(h));
        size_t o = (size_t)(n0 + r) * 256 + k0 + threadIdx.x;
        d_Wth[o] = h;
        d_Wtl[o] = l;
    }
}

// ---------------------------------------------------------------------------
// Kernel 3: pooling — one warp per segment, online softmax, registers only.
// ---------------------------------------------------------------------------
__global__ __launch_bounds__(256) void pool_kernel(
    const float* __restrict__ x,
    const float* __restrict__ wts,
    const float* __restrict__ Wg,
    const float* __restrict__ bg,
    const float* __restrict__ p,
    int S)
{
    const int s = blockIdx.x * 8 + (threadIdx.x >> 5);
    if (s >= S) return;
    const int lane = threadIdx.x & 31;

    const float4* __restrict__ x4 = (const float4*)x;
    const float4 wg0 = ((const float4*)Wg)[lane];
    const float4 wg1 = ((const float4*)Wg)[lane + 32];
    const float bg0 = bg[0];
    const float p0  = p[0];

    const int beg = d_segstart[s];
    const int cnt = d_segstart[s + 1] - beg;

    float4 a0 = make_float4(0.f, 0.f, 0.f, 0.f);
    float4 a1 = make_float4(0.f, 0.f, 0.f, 0.f);
    float m = -INFINITY, den = 0.0f;

    float4 c0 = make_float4(0.f, 0.f, 0.f, 0.f);
    float4 c1 = make_float4(0.f, 0.f, 0.f, 0.f);
    float cw = 1.0f;
    if (cnt > 0) {
        size_t b = (size_t)beg * 64;
        c0 = x4[b + lane];
        c1 = x4[b + 32 + lane];
        cw = wts[beg];
    }

    for (int i = 0; i < cnt; i++) {
        float4 n0v = make_float4(0.f, 0.f, 0.f, 0.f);
        float4 n1v = make_float4(0.f, 0.f, 0.f, 0.f);
        float nw = 1.0f;
        if (i + 1 < cnt) {
            size_t b = (size_t)(beg + i + 1) * 64;
            n0v = x4[b + lane];
            n1v = x4[b + 32 + lane];
            nw = wts[beg + i + 1];
        }

        float dot = c0.x * wg0.x + c0.y * wg0.y + c0.z * wg0.z + c0.w * wg0.w
                  + c1.x * wg1.x + c1.y * wg1.y + c1.z * wg1.z + c1.w * wg1.w;
        #pragma unroll
        for (int o = 16; o; o >>= 1)
            dot += __shfl_xor_sync(0xffffffffu, dot, o);
        const float lg = dot + bg0;

        const float nm = fmaxf(m, lg);
        const float sc = ex2f((m - nm) * L2E);
        const float e  = ex2f(fmaf(p0, lg2f(cw), (lg - nm) * L2E));
        den = den * sc + e;
        a0.x = fmaf(e, c0.x, a0.x * sc);
        a0.y = fmaf(e, c0.y, a0.y * sc);
        a0.z = fmaf(e, c0.z, a0.z * sc);
        a0.w = fmaf(e, c0.w, a0.w * sc);
        a1.x = fmaf(e, c1.x, a1.x * sc);
        a1.y = fmaf(e, c1.y, a1.y * sc);
        a1.z = fmaf(e, c1.z, a1.z * sc);
        a1.w = fmaf(e, c1.w, a1.w * sc);
        m = nm;

        c0 = n0v; c1 = n1v; cw = nw;
    }

    const float inv = 1.0f / (den + 1e-10f);
    float4 r0, r1;
    r0.x = a0.x * inv; r0.y = a0.y * inv; r0.z = a0.z * inv; r0.w = a0.w * inv;
    r1.x = a1.x * inv; r1.y = a1.y * inv; r1.z = a1.z * inv; r1.w = a1.w * inv;

    {
        __nv_bfloat162 h01 = __floats2bfloat162_rn(r0.x, r0.y);
        __nv_bfloat162 h23 = __floats2bfloat162_rn(r0.z, r0.w);
        __nv_bfloat162 l01 = __floats2bfloat162_rn(r0.x - __bfloat162float(h01.x),
                                                   r0.y - __bfloat162float(h01.y));
        __nv_bfloat162 l23 = __floats2bfloat162_rn(r0.z - __bfloat162float(h23.x),
                                                   r0.w - __bfloat162float(h23.y));
        size_t o = (size_t)s * 256 + 4 * lane;
        uint2 uh, ul;
        memcpy(&uh.x, &h01, 4); memcpy(&uh.y, &h23, 4);
        memcpy(&ul.x, &l01, 4); memcpy(&ul.y, &l23, 4);
        *(uint2*)&d_ph[o] = uh;
        *(uint2*)&d_pl[o] = ul;
    }
    {
        __nv_bfloat162 h01 = __floats2bfloat162_rn(r1.x, r1.y);
        __nv_bfloat162 h23 = __floats2bfloat162_rn(r1.z, r1.w);
        __nv_bfloat162 l01 = __floats2bfloat162_rn(r1.x - __bfloat162float(h01.x),
                                                   r1.y - __bfloat162float(h01.y));
        __nv_bfloat162 l23 = __floats2bfloat162_rn(r1.z - __bfloat162float(h23.x),
                                                   r1.w - __bfloat162float(h23.y));
        size_t o = (size_t)s * 256 + 128 + 4 * lane;
        uint2 uh, ul;
        memcpy(&uh.x, &h01, 4); memcpy(&uh.y, &h23, 4);
        memcpy(&ul.x, &l01, 4); memcpy(&ul.y, &l23, 4);
        *(uint2*)&d_ph[o] = uh;
        *(uint2*)&d_pl[o] = ul;
    }
    if (lane == 0) d_gsum[s] = den * inv;
}

// ---------------------------------------------------------------------------
// Kernel 4: split-bf16 HMMA GEMM, occupancy-tuned.
// Block tile 128x64 (512 thr, 4x4 warp grid, warp tile 32x16), K-step 32,
// cp.async double buffered. Regs ~54 -> 2 CTAs/SM (50% occ).
// ---------------------------------------------------------------------------
#define GM 128
#define GN 64
#define AK 40                       // bf16 per padded smem row (32 + 8)
#define A_TILE (128 * AK * 2)       // 10240 B
#define B_TILE (64 * AK * 2)        // 5120 B
#define STAGE  (2 * A_TILE + 2 * B_TILE)   // 30720 B
// within a stage: Ah @0, Al @A_TILE, Bh @2*A_TILE, Bl @2*A_TILE+B_TILE

#define MMA_BF16(d, a, b)                                                     \
    asm volatile(                                                             \
        "mma.sync.aligned.m16n8k16.row.col.f32.bf16.bf16.f32 "                \
        "{%0,%1,%2,%3}, {%4,%5,%6,%7}, {%8,%9}, {%0,%1,%2,%3};"               \
        : "+f"((d)[0]), "+f"((d)[1]), "+f"((d)[2]), "+f"((d)[3])              \
        : "r"((a)[0]), "r"((a)[1]), "r"((a)[2]), "r"((a)[3]),                 \
          "r"((b)[0]), "r"((b)[1]))

__device__ __forceinline__ void ldsm_x4(unsigned& r0, unsigned& r1,
                                        unsigned& r2, unsigned& r3,
                                        unsigned addr) {
    asm volatile("ldmatrix.sync.aligned.m8n8.x4.shared.b16 {%0,%1,%2,%3}, [%4];"
                 : "=r"(r0), "=r"(r1), "=r"(r2), "=r"(r3) : "r"(addr));
}
__device__ __forceinline__ void cp16(unsigned dst, const void* src, int sz) {
    asm volatile("cp.async.cg.shared.global [%0], [%1], 16, %2;"
                 :: "r"(dst), "l"(src), "r"(sz));
}

__global__ __launch_bounds__(512, 2) void gemm_mma_kernel(
    const float* __restrict__ bm,
    float* __restrict__ out,
    int S)
{
    extern __shared__ char smem[];
    const unsigned sbase = (unsigned)__cvta_generic_to_shared(smem);

    const int tid  = threadIdx.x;
    const int warp = tid >> 5, lane = tid & 31;
    const int g = lane >> 2, t = lane & 3;
    const int wm = warp >> 2;          // 0..3 (M)
    const int wn = warp & 3;           // 0..3 (N)
    const int m0 = blockIdx.x * GM;
    const int n0 = blockIdx.y * GN;

    float acc[2][2][4] = {};           // [m16 tile][n8 frag][regs]

    // ---- loader mapping ----
    // A: thread -> (row = tid>>2, 16B chunk = tid&3); loads Ah + Al.
    const int lrow = tid >> 2;         // 0..127
    const int lchk = tid & 3;          // 0..3
    int arow = m0 + lrow;
    const int asz = (arow < S) ? 16 : 0;
    if (arow >= S) arow = 0;
    const unsigned a_dst = (unsigned)(lrow * (AK * 2) + lchk * 16);
    // B: 512 chunk slots: hl = tid>>8, row = (tid&255)>>2, chunk = tid&3.
    const int b_hl  = tid >> 8;
    const int b_row = (tid & 255) >> 2;
    const int b_chk = tid & 3;
    const unsigned b_dst = (unsigned)(2 * A_TILE + b_hl * B_TILE
                                      + b_row * (AK * 2) + b_chk * 16);
    const __nv_bfloat16* __restrict__ bsrc = b_hl ? d_Wtl : d_Wth;

    // ---- ldmatrix per-lane invariant offsets (bytes) ----
    unsigned a_off[2];
    #pragma unroll
    for (int i = 0; i < 2; i++)
        a_off[i] = (unsigned)((wm * 32 + i * 16 + (lane & 15)) * (AK * 2)
                              + (lane >> 4) * 16);
    const unsigned b_off =
        (unsigned)((wn * 16 + ((lane >> 4) << 3) + (lane & 7)) * (AK * 2)
                   + (((lane >> 3) & 1) << 4));

    auto load_stage = [&](int it) {
        const int kb = it * 32;
        const unsigned sb = sbase + (unsigned)((it & 1) * STAGE);
        cp16(sb + a_dst,          &d_ph[(size_t)arow * 256 + kb + lchk * 8], asz);
        cp16(sb + A_TILE + a_dst, &d_pl[(size_t)arow * 256 + kb + lchk * 8], asz);
        cp16(sb + b_dst, &bsrc[(size_t)(n0 + b_row) * 256 + kb + b_chk * 8], 16);
        asm volatile("cp.async.commit_group;");
    };

    load_stage(0);
    load_stage(1);

    #pragma unroll
    for (int it = 0; it < 8; it++) {
        if (it < 6) asm volatile("cp.async.wait_group 1;");
        else        asm volatile("cp.async.wait_group 0;");
        __syncthreads();

        const unsigned sb = sbase + (unsigned)((it & 1) * STAGE);

        #pragma unroll
        for (int kk = 0; kk < 2; kk++) {
            const unsigned kadd = kk * 32;   // 16 bf16 = 32 bytes

            unsigned ah[2][4], al[2][4];
            #pragma unroll
            for (int i = 0; i < 2; i++) {
                ldsm_x4(ah[i][0], ah[i][1], ah[i][2], ah[i][3],
                        sb + a_off[i] + kadd);
                ldsm_x4(al[i][0], al[i][1], al[i][2], al[i][3],
                        sb + A_TILE + a_off[i] + kadd);
            }
            unsigned bh[2][2], bl[2][2];
            {
                unsigned r0, r1, r2, r3;
                ldsm_x4(r0, r1, r2, r3, sb + 2 * A_TILE + b_off + kadd);
                bh[0][0] = r0; bh[0][1] = r1; bh[1][0] = r2; bh[1][1] = r3;
                ldsm_x4(r0, r1, r2, r3, sb + 2 * A_TILE + B_TILE + b_off + kadd);
                bl[0][0] = r0; bl[0][1] = r1; bl[1][0] = r2; bl[1][1] = r3;
            }

            #pragma unroll
            for (int i = 0; i < 2; i++)
                #pragma unroll
                for (int j = 0; j < 2; j++) {
                    MMA_BF16(acc[i][j], ah[i], bh[j]);
                    MMA_BF16(acc[i][j], ah[i], bl[j]);
                    MMA_BF16(acc[i][j], al[i], bh[j]);
                }
        }
        __syncthreads();
        if (it + 2 < 8) load_stage(it + 2);
    }

    // ---- epilogue: + gsum[m] * bm[n] ----
    #pragma unroll
    for (int i = 0; i < 2; i++) {
        #pragma unroll
        for (int rr = 0; rr < 2; rr++) {
            const int mrow = m0 + wm * 32 + i * 16 + g + rr * 8;
            if (mrow < S) {
                const float gs = d_gsum[mrow];
                #pragma unroll
                for (int j = 0; j < 2; j++) {
                    const int n = n0 + wn * 16 + j * 8 + 2 * t;
                    float2 o;
                    o.x = acc[i][j][rr * 2 + 0] + gs * bm[n];
                    o.y = acc[i][j][rr * 2 + 1] + gs * bm[n + 1];
                    *(float2*)&out[(size_t)mrow * 256 + n] = o;
                }
            }
        }
    }
}

// ---------------------------------------------------------------------------
// Inputs: x, weights, Wg, bg, Wm, bm, p, index, num_segments
// ---------------------------------------------------------------------------
extern "C" void kernel_launch(void* const* d_in, const int* in_sizes, int n_in,
                              void* d_out, int out_size) {
    const float* x     = (const float*)d_in[0];
    const float* wts   = (const float*)d_in[1];
    const float* Wg    = (const float*)d_in[2];
    const float* bg    = (const float*)d_in[3];
    const float* Wm    = (const float*)d_in[4];
    const float* bm    = (const float*)d_in[5];
    const float* p     = (const float*)d_in[6];
    const int*   index = (const int*)d_in[7];

    const int N = in_sizes[7];
    const int S = out_size / 256;
    const int smem_bytes = 2 * STAGE;   // 61440

    cudaFuncSetAttribute(gemm_mma_kernel,
                         cudaFuncAttributeMaxDynamicSharedMemorySize, smem_bytes);

    seg_bounds_kernel<<<(N / 4 + 256) / 256, 256>>>(index, N, S);
    prep_kernel<<<dim3(8, 8), dim3(32, 8)>>>(Wm);
    pool_kernel<<<(S + 7) / 8, 256>>>(x, wts, Wg, bg, p, S);
    gemm_mma_kernel<<<dim3((S + GM - 1) / GM, 256 / GN), 512, smem_bytes>>>(
        bm, (float*)d_out, S);
}